// round 7
// baseline (speedup 1.0000x reference)
#include <cuda_runtime.h>
#include <stdint.h>

#define EMB    128
#define HEADS  4
#define MAXN   50000
#define MAXE   600000

// Flip to 0 if the toolchain rejects red.global.add.v4.f32 (PTX ISA 8.1+).
#define USE_V4_RED 1

// Scratch: Q | K | V node projections, per-edge exp(att), per-node softmax denom.
__device__ float g_P[3ull * MAXN * EMB];          // 76.8 MB
__device__ float g_expAtt[(size_t)MAXE * HEADS];  // 9.6 MB
__device__ float g_attNorm[(size_t)MAXN * HEADS]; // 0.8 MB

// ---------------- packed f32x2 helpers (Blackwell FFMA2) ----------------
__device__ __forceinline__ unsigned long long fma2(unsigned long long a,
                                                   unsigned long long b,
                                                   unsigned long long c) {
    unsigned long long d;
    asm("fma.rn.f32x2 %0, %1, %2, %3;" : "=l"(d) : "l"(a), "l"(b), "l"(c));
    return d;
}
__device__ __forceinline__ void unpack2(unsigned long long v, float& lo, float& hi) {
    asm("mov.b64 {%0, %1}, %2;" : "=f"(lo), "=f"(hi) : "l"(v));
}

// no-return scalar global reduction
__device__ __forceinline__ void red_add_f32(float* p, float v) {
    asm volatile("red.global.add.f32 [%0], %1;" :: "l"(p), "f"(v) : "memory");
}
// vectorized global reduction: 1 op moves 16B
__device__ __forceinline__ void red_add_v4f32(float* p, float a, float b, float c, float d) {
#if USE_V4_RED
    asm volatile("red.global.add.v4.f32 [%0], {%1, %2, %3, %4};"
                 :: "l"(p), "f"(a), "f"(b), "f"(c), "f"(d) : "memory");
#else
    red_add_f32(p + 0, a);
    red_add_f32(p + 1, b);
    red_add_f32(p + 2, c);
    red_add_f32(p + 3, d);
#endif
}

// ---------------- Phase 1: node projection GEMM ----------------
// C[N,384] = A[N,128] @ [qW | kW | vW]   (each W is [128,128] row-major)
// BM=64, BN=64, BK=16, 256 threads (16x16), each thread computes 4x4 via FFMA2.
#define BM 64
#define BN 64
#define BK 16

__global__ __launch_bounds__(256) void proj_kernel(
    const float* __restrict__ A,
    const float* __restrict__ qW,
    const float* __restrict__ kW,
    const float* __restrict__ vW,
    int Nn)
{
    __shared__ float As[BK][BM + 4];     // transposed A tile, padded
    __shared__ float Bs2[BK * 2 * BN];   // duplicated B pairs: col c at [k][(c%4)*32 + (c/4)*2]

    const int by    = blockIdx.y;                 // 0..5 -> which W / which half
    const int brow  = blockIdx.x * BM;
    const float* W  = (by < 2) ? qW : (by < 4) ? kW : vW;
    const int wcol0 = (by & 1) * BN;
    float* C = g_P + (size_t)(by >> 1) * MAXN * EMB;

    const int tid = threadIdx.x;
    const int tx  = tid & 15;     // output col group (4 cols)
    const int ty  = tid >> 4;     // output row group (4 rows)

    const int arow = tid >> 2;    // A-load: row 0..63
    const int aseg = tid & 3;     // A-load: k segment of 4
    const int bk   = tid >> 4;    // B-load: k row 0..15
    const int bseg = tid & 15;    // B-load: col segment of 4

    const int  grow    = brow + arow;
    const bool arow_ok = (grow < Nn);
    const float* Arow  = A + (size_t)grow * EMB;

    unsigned long long acc[2][4] = {};   // [row-pair][col]

    for (int k0 = 0; k0 < EMB; k0 += BK) {
        float4 av = make_float4(0.f, 0.f, 0.f, 0.f);
        if (arow_ok) av = *(const float4*)(Arow + k0 + aseg * 4);
        As[aseg * 4 + 0][arow] = av.x;
        As[aseg * 4 + 1][arow] = av.y;
        As[aseg * 4 + 2][arow] = av.z;
        As[aseg * 4 + 3][arow] = av.w;

        float4 bv = *(const float4*)(W + (size_t)(k0 + bk) * EMB + wcol0 + bseg * 4);
        {
            float* base = &Bs2[bk * (2 * BN)];
            *(float2*)&base[0 * 32 + bseg * 2] = make_float2(bv.x, bv.x);
            *(float2*)&base[1 * 32 + bseg * 2] = make_float2(bv.y, bv.y);
            *(float2*)&base[2 * 32 + bseg * 2] = make_float2(bv.z, bv.z);
            *(float2*)&base[3 * 32 + bseg * 2] = make_float2(bv.w, bv.w);
        }
        __syncthreads();

        #pragma unroll
        for (int k = 0; k < BK; ++k) {
            unsigned long long ap0 = *(const unsigned long long*)&As[k][ty * 4 + 0];
            unsigned long long ap1 = *(const unsigned long long*)&As[k][ty * 4 + 2];
            const float* base = &Bs2[k * (2 * BN)];
            #pragma unroll
            for (int j = 0; j < 4; ++j) {
                unsigned long long bs = *(const unsigned long long*)&base[j * 32 + tx * 2];
                acc[0][j] = fma2(ap0, bs, acc[0][j]);
                acc[1][j] = fma2(ap1, bs, acc[1][j]);
            }
        }
        __syncthreads();
    }

    #pragma unroll
    for (int i = 0; i < 2; ++i) {
        float lo[4], hi[4];
        #pragma unroll
        for (int j = 0; j < 4; ++j) unpack2(acc[i][j], lo[j], hi[j]);
        int r0 = brow + ty * 4 + i * 2;
        if (r0 < Nn)
            *(float4*)(C + (size_t)r0 * EMB + wcol0 + tx * 4) =
                make_float4(lo[0], lo[1], lo[2], lo[3]);
        if (r0 + 1 < Nn)
            *(float4*)(C + (size_t)(r0 + 1) * EMB + wcol0 + tx * 4) =
                make_float4(hi[0], hi[1], hi[2], hi[3]);
    }
}

// ---------------- Phase 2: per-edge logits + softmax denominator ----------------
// 1 warp per edge. Lane l covers floats 4l..4l+3; head h = lanes 8h..8h+7.
__global__ __launch_bounds__(256) void edge_logits_kernel(
    const int* __restrict__ rows, const int* __restrict__ cols, int E)
{
    int warp = (blockIdx.x * blockDim.x + threadIdx.x) >> 5;
    int lane = threadIdx.x & 31;
    if (warp >= E) return;

    int r = __ldg(rows + warp);
    int c = __ldg(cols + warp);

    const float4* Qr = (const float4*)(g_P + (size_t)r * EMB);
    const float4* Kr = (const float4*)(g_P + (size_t)MAXN * EMB + (size_t)c * EMB);
    float4 q = __ldg(Qr + lane);
    float4 k = __ldg(Kr + lane);

    float p = q.x * k.x + q.y * k.y + q.z * k.z + q.w * k.w;
    p += __shfl_down_sync(0xffffffffu, p, 4, 8);
    p += __shfl_down_sync(0xffffffffu, p, 2, 8);
    p += __shfl_down_sync(0xffffffffu, p, 1, 8);

    if ((lane & 7) == 0) {
        int h = lane >> 3;
        p = fminf(fmaxf(p, -10.0f), 10.0f);
        float ea = expf(p);
        g_expAtt[(size_t)warp * HEADS + h] = ea;
        red_add_f32(&g_attNorm[(size_t)r * HEADS + h], ea);
    }
}

// ---------------- Phase 3: normalize + weighted scatter of V ----------------
__global__ __launch_bounds__(256) void edge_aggregate_kernel(
    const int* __restrict__ rows, const int* __restrict__ cols,
    float* __restrict__ out, int E)
{
    int warp = (blockIdx.x * blockDim.x + threadIdx.x) >> 5;
    int lane = threadIdx.x & 31;
    if (warp >= E) return;

    int r = __ldg(rows + warp);
    int c = __ldg(cols + warp);
    int h = lane >> 3;

    float ea   = g_expAtt[(size_t)warp * HEADS + h];
    float nrm  = g_attNorm[(size_t)r * HEADS + h];
    float coef = ea / (nrm + 1e-8f);

    const float4* Vr = (const float4*)(g_P + 2ull * MAXN * EMB + (size_t)c * EMB);
    float4 v = __ldg(Vr + lane);

    float* o = out + (size_t)r * EMB + lane * 4;   // 16B-aligned
    red_add_v4f32(o, coef * v.x, coef * v.y, coef * v.z, coef * v.w);
}

// ---------------- launch ----------------
extern "C" void kernel_launch(void* const* d_in, const int* in_sizes, int n_in,
                              void* d_out, int out_size)
{
    const float* embeds = (const float*)d_in[0];
    const float* qW     = (const float*)d_in[1];
    const float* kW     = (const float*)d_in[2];
    const float* vW     = (const float*)d_in[3];
    const int*   rows   = (const int*)d_in[4];
    const int*   cols   = (const int*)d_in[5];

    int Nn = in_sizes[0] / EMB;
    int E  = in_sizes[4];
    float* out = (float*)d_out;

    // Cache symbol address (host-side query, not a stream op).
    static void* attNormPtr = nullptr;
    if (!attNormPtr) cudaGetSymbolAddress(&attNormPtr, g_attNorm);

    // zero the accumulators (out is poisoned by harness)
    cudaMemsetAsync(attNormPtr, 0, (size_t)Nn * HEADS * sizeof(float), 0);
    cudaMemsetAsync(out, 0, (size_t)out_size * sizeof(float), 0);

    // Phase 1: node projections Q,K,V
    dim3 pgrid((Nn + BM - 1) / BM, (3 * EMB) / BN);
    proj_kernel<<<pgrid, 256>>>(embeds, qW, kW, vW, Nn);

    // Phase 2: edge logits + softmax denominators
    int eblocks = (E + 7) / 8;   // 8 warps per 256-thread block
    edge_logits_kernel<<<eblocks, 256>>>(rows, cols, E);

    // Phase 3: normalize + scatter
    edge_aggregate_kernel<<<eblocks, 256>>>(rows, cols, out, E);
}

// round 14
// speedup vs baseline: 1.2595x; 1.2595x over previous
#include <cuda_runtime.h>
#include <stdint.h>

#define EMB    128
#define HEADS  4
#define MAXN   50000
#define MAXE   600000

#define USE_V4_RED 1

// Scratch: Q | K | V node projections, per-edge exp(att), per-node softmax denom.
__device__ float g_P[3ull * MAXN * EMB];          // 76.8 MB
__device__ float g_expAtt[(size_t)MAXE * HEADS];  // 9.6 MB
__device__ float g_attNorm[(size_t)MAXN * HEADS]; // 0.8 MB

// ---------------- packed f32x2 helpers (Blackwell FFMA2) ----------------
__device__ __forceinline__ unsigned long long fma2(unsigned long long a,
                                                   unsigned long long b,
                                                   unsigned long long c) {
    unsigned long long d;
    asm("fma.rn.f32x2 %0, %1, %2, %3;" : "=l"(d) : "l"(a), "l"(b), "l"(c));
    return d;
}
__device__ __forceinline__ void unpack2(unsigned long long v, float& lo, float& hi) {
    asm("mov.b64 {%0, %1}, %2;" : "=f"(lo), "=f"(hi) : "l"(v));
}
__device__ __forceinline__ unsigned long long splat2(float x) {
    unsigned long long d;
    unsigned int u = __float_as_uint(x);
    asm("mov.b64 %0, {%1, %1};" : "=l"(d) : "r"(u));
    return d;
}

// no-return global reductions
__device__ __forceinline__ void red_add_f32(float* p, float v) {
    asm volatile("red.global.add.f32 [%0], %1;" :: "l"(p), "f"(v) : "memory");
}
__device__ __forceinline__ void red_add_v4f32(float* p, float a, float b, float c, float d) {
#if USE_V4_RED
    asm volatile("red.global.add.v4.f32 [%0], {%1, %2, %3, %4};"
                 :: "l"(p), "f"(a), "f"(b), "f"(c), "f"(d) : "memory");
#else
    red_add_f32(p + 0, a);
    red_add_f32(p + 1, b);
    red_add_f32(p + 2, c);
    red_add_f32(p + 3, d);
#endif
}

// ---------------- Phase 1: node projection GEMM ----------------
// C[N,384] = A[N,128] @ [qW | kW | vW].
// BM=128, BN=64, BK=16, 256 threads (16x16). Each thread: 8 rows x 4 cols via
// FFMA2 (4 row-pairs). Per k: A = 2x LDS.128 (32B), B = 1x LDS.128 (16B) +
// 4 register splats -> 3 B smem per FFMA2 (was 6 with the duplicated-B layout).
#define BM 128
#define BN 64
#define BK 16

__global__ __launch_bounds__(256) void proj_kernel(
    const float* __restrict__ A,
    const float* __restrict__ qW,
    const float* __restrict__ kW,
    const float* __restrict__ vW,
    int Nn)
{
    __shared__ __align__(16) float As[BK][BM + 4];  // transposed A tile (k-major), padded
    __shared__ __align__(16) float Bs[BK][BN];      // plain B tile

    const int by    = blockIdx.y;                 // 0..5 -> which W / which half
    const int brow  = blockIdx.x * BM;
    const float* W  = (by < 2) ? qW : (by < 4) ? kW : vW;
    const int wcol0 = (by & 1) * BN;
    float* C = g_P + (size_t)(by >> 1) * MAXN * EMB;

    const int tid = threadIdx.x;
    const int tx  = tid & 15;     // output col group (4 cols)
    const int ty  = tid >> 4;     // output row group (8 rows)

    // A-load mapping: 2 float4 per thread (row = tid>>1, segs 2*(tid&1)+{0,1})
    const int arow  = tid >> 1;           // 0..127
    const int aseg0 = (tid & 1) * 2;      // 0 or 2 (of 4 k-segments)
    // B-load mapping: 1 float4 per thread
    const int bk   = tid >> 4;            // 0..15
    const int bseg = tid & 15;            // col segment of 4

    const int  grow    = brow + arow;
    const bool arow_ok = (grow < Nn);
    const float* Arow  = A + (size_t)grow * EMB;

    unsigned long long acc[4][4] = {};    // [row-pair][col]

    for (int k0 = 0; k0 < EMB; k0 += BK) {
        // --- load A tile (transposed) ---
        #pragma unroll
        for (int s = 0; s < 2; ++s) {
            int seg = aseg0 + s;
            float4 av = make_float4(0.f, 0.f, 0.f, 0.f);
            if (arow_ok) av = *(const float4*)(Arow + k0 + seg * 4);
            As[seg * 4 + 0][arow] = av.x;
            As[seg * 4 + 1][arow] = av.y;
            As[seg * 4 + 2][arow] = av.z;
            As[seg * 4 + 3][arow] = av.w;
        }
        // --- load B tile (plain) ---
        *(float4*)&Bs[bk][bseg * 4] =
            *(const float4*)(W + (size_t)(k0 + bk) * EMB + wcol0 + bseg * 4);
        __syncthreads();

        #pragma unroll
        for (int k = 0; k < BK; ++k) {
            // A: 8 rows = 4 packed pairs via 2x LDS.128
            const ulonglong2* pa = (const ulonglong2*)&As[k][ty * 8];
            ulonglong2 a01 = pa[0];
            ulonglong2 a23 = pa[1];
            unsigned long long ap[4] = { a01.x, a01.y, a23.x, a23.y };
            // B: 4 cols via 1x LDS.128, splat to f32x2
            float4 b4 = *(const float4*)&Bs[k][tx * 4];
            unsigned long long bsp[4] = { splat2(b4.x), splat2(b4.y),
                                          splat2(b4.z), splat2(b4.w) };
            #pragma unroll
            for (int p = 0; p < 4; ++p)
                #pragma unroll
                for (int j = 0; j < 4; ++j)
                    acc[p][j] = fma2(ap[p], bsp[j], acc[p][j]);
        }
        __syncthreads();
    }

    // --- write 8x4 microtile ---
    #pragma unroll
    for (int p = 0; p < 4; ++p) {
        float lo[4], hi[4];
        #pragma unroll
        for (int j = 0; j < 4; ++j) unpack2(acc[p][j], lo[j], hi[j]);
        int r0 = brow + ty * 8 + p * 2;
        if (r0 < Nn)
            *(float4*)(C + (size_t)r0 * EMB + wcol0 + tx * 4) =
                make_float4(lo[0], lo[1], lo[2], lo[3]);
        if (r0 + 1 < Nn)
            *(float4*)(C + (size_t)(r0 + 1) * EMB + wcol0 + tx * 4) =
                make_float4(hi[0], hi[1], hi[2], hi[3]);
    }
}

// ---------------- Phase 2: per-edge logits + softmax denominator ----------------
// 1 warp per edge. Lane l covers floats 4l..4l+3; head h = lanes 8h..8h+7.
__global__ __launch_bounds__(256) void edge_logits_kernel(
    const int* __restrict__ rows, const int* __restrict__ cols, int E)
{
    int warp = (blockIdx.x * blockDim.x + threadIdx.x) >> 5;
    int lane = threadIdx.x & 31;
    if (warp >= E) return;

    int r = __ldg(rows + warp);
    int c = __ldg(cols + warp);

    const float4* Qr = (const float4*)(g_P + (size_t)r * EMB);
    const float4* Kr = (const float4*)(g_P + (size_t)MAXN * EMB + (size_t)c * EMB);
    float4 q = __ldg(Qr + lane);
    float4 k = __ldg(Kr + lane);

    float p = q.x * k.x + q.y * k.y + q.z * k.z + q.w * k.w;
    p += __shfl_down_sync(0xffffffffu, p, 4, 8);
    p += __shfl_down_sync(0xffffffffu, p, 2, 8);
    p += __shfl_down_sync(0xffffffffu, p, 1, 8);

    if ((lane & 7) == 0) {
        int h = lane >> 3;
        p = fminf(fmaxf(p, -10.0f), 10.0f);
        float ea = expf(p);
        g_expAtt[(size_t)warp * HEADS + h] = ea;
        red_add_f32(&g_attNorm[(size_t)r * HEADS + h], ea);
    }
}

// ---------------- Phase 3: normalize + weighted scatter of V ----------------
__global__ __launch_bounds__(256) void edge_aggregate_kernel(
    const int* __restrict__ rows, const int* __restrict__ cols,
    float* __restrict__ out, int E)
{
    int warp = (blockIdx.x * blockDim.x + threadIdx.x) >> 5;
    int lane = threadIdx.x & 31;
    if (warp >= E) return;

    int r = __ldg(rows + warp);
    int c = __ldg(cols + warp);
    int h = lane >> 3;

    float ea   = g_expAtt[(size_t)warp * HEADS + h];
    float nrm  = g_attNorm[(size_t)r * HEADS + h];
    float coef = ea / (nrm + 1e-8f);

    const float4* Vr = (const float4*)(g_P + 2ull * MAXN * EMB + (size_t)c * EMB);
    float4 v = __ldg(Vr + lane);

    float* o = out + (size_t)r * EMB + lane * 4;   // 16B-aligned
    red_add_v4f32(o, coef * v.x, coef * v.y, coef * v.z, coef * v.w);
}

// ---------------- launch ----------------
extern "C" void kernel_launch(void* const* d_in, const int* in_sizes, int n_in,
                              void* d_out, int out_size)
{
    const float* embeds = (const float*)d_in[0];
    const float* qW     = (const float*)d_in[1];
    const float* kW     = (const float*)d_in[2];
    const float* vW     = (const float*)d_in[3];
    const int*   rows   = (const int*)d_in[4];
    const int*   cols   = (const int*)d_in[5];

    int Nn = in_sizes[0] / EMB;
    int E  = in_sizes[4];
    float* out = (float*)d_out;

    // Cache symbol address (host-side query, not a stream op).
    static void* attNormPtr = nullptr;
    if (!attNormPtr) cudaGetSymbolAddress(&attNormPtr, g_attNorm);

    // zero the accumulators (out is poisoned by harness)
    cudaMemsetAsync(attNormPtr, 0, (size_t)Nn * HEADS * sizeof(float), 0);
    cudaMemsetAsync(out, 0, (size_t)out_size * sizeof(float), 0);

    // Phase 1: node projections Q,K,V
    dim3 pgrid((Nn + BM - 1) / BM, (3 * EMB) / BN);
    proj_kernel<<<pgrid, 256>>>(embeds, qW, kW, vW, Nn);

    // Phase 2: edge logits + softmax denominators
    int eblocks = (E + 7) / 8;   // 8 warps per 256-thread block
    edge_logits_kernel<<<eblocks, 256>>>(rows, cols, E);

    // Phase 3: normalize + scatter
    edge_aggregate_kernel<<<eblocks, 256>>>(rows, cols, out, E);
}